// round 13
// baseline (speedup 1.0000x reference)
#include <cuda_runtime.h>
#include <cuda_bf16.h>
#include <cstdint>

#define BATCH   8192
#define NF      128
#define NH      64
#define THREADS 256
#define MAXPH   256

#define BSTRIDE 136                       // bf16 elems per smem tile row (pad 8)
#define TILE_BYTES (128 * BSTRIDE * 2)    // 34816 B
#define OFF_AH  0
#define OFF_AL  (TILE_BYTES)
#define OFF_BH  (2 * TILE_BYTES)
#define OFF_BL  (3 * TILE_BYTES)
#define SMEM_BYTES (4 * TILE_BYTES)       // 139264 B

__device__ int g_rows[NH * MAXPH];
__device__ int g_cnt[NH];

__device__ __forceinline__ uint32_t smem_u32(const void* p) {
    return (uint32_t)__cvta_generic_to_shared(p);
}
__device__ __forceinline__ unsigned pack2(__nv_bfloat16 a, __nv_bfloat16 b) {
    return (unsigned)__bfloat16_as_ushort(a) | ((unsigned)__bfloat16_as_ushort(b) << 16);
}

#define LDSM_X4(r0, r1, r2, r3, addr) \
    asm volatile("ldmatrix.sync.aligned.m8n8.x4.shared.b16 {%0,%1,%2,%3}, [%4];" \
                 : "=r"(r0), "=r"(r1), "=r"(r2), "=r"(r3) : "r"(addr))
#define LDSM_X4T(r0, r1, r2, r3, addr) \
    asm volatile("ldmatrix.sync.aligned.m8n8.x4.trans.shared.b16 {%0,%1,%2,%3}, [%4];" \
                 : "=r"(r0), "=r"(r1), "=r"(r2), "=r"(r3) : "r"(addr))

__device__ __forceinline__ void mma_bf16(float* c,
    uint32_t a0, uint32_t a1, uint32_t a2, uint32_t a3, uint32_t b0, uint32_t b1) {
    asm volatile(
        "mma.sync.aligned.m16n8k16.row.col.f32.bf16.bf16.f32 "
        "{%0,%1,%2,%3}, {%4,%5,%6,%7}, {%8,%9}, {%0,%1,%2,%3};"
        : "+f"(c[0]), "+f"(c[1]), "+f"(c[2]), "+f"(c[3])
        : "r"(a0), "r"(a1), "r"(a2), "r"(a3), "r"(b0), "r"(b1));
}

// ---------------------------------------------------------------------------
// Prep (validated R10/R11): one CTA per head; dtype-detect head_ix, build
// ordered per-head row lists in g_rows/g_cnt.
// ---------------------------------------------------------------------------
__global__ void __launch_bounds__(THREADS) lm_prep(const void* __restrict__ hx) {
    __shared__ int s_wtot[8], s_woff[8], s_n;
    const int tid = threadIdx.x, warp = tid >> 5, lane = tid & 31;
    const int h = blockIdx.x;

    const unsigned* wd = (const unsigned*)hx;
    unsigned a = 0;
    #pragma unroll
    for (int m = 0; m < 8; m++) a |= wd[2 * (tid + m * THREADS) + 1];
    const int is32 = __syncthreads_or(a != 0);

    union { unsigned v[8]; unsigned char b[32]; } u;
    if (is32) {
        const int4* p = (const int4*)hx;
        #pragma unroll
        for (int j = 0; j < 8; j++) {
            int4 q = p[tid * 8 + j];
            u.v[j] = (unsigned)q.x | ((unsigned)q.y << 8) |
                     ((unsigned)q.z << 16) | ((unsigned)q.w << 24);
        }
    } else {
        const ulonglong2* p = (const ulonglong2*)hx;
        #pragma unroll
        for (int j = 0; j < 8; j++) {
            ulonglong2 q0 = p[tid * 16 + 2 * j];
            ulonglong2 q1 = p[tid * 16 + 2 * j + 1];
            u.v[j] = (unsigned)(q0.x & 0xff) | ((unsigned)(q0.y & 0xff) << 8) |
                     ((unsigned)(q1.x & 0xff) << 16) | ((unsigned)(q1.y & 0xff) << 24);
        }
    }

    int cnt = 0;
    #pragma unroll
    for (int j = 0; j < 32; j++) cnt += (u.b[j] == h);
    int pre = cnt;
    #pragma unroll
    for (int off = 1; off < 32; off <<= 1) {
        int t = __shfl_up_sync(~0u, pre, off);
        if (lane >= off) pre += t;
    }
    if (lane == 31) s_wtot[warp] = pre;
    __syncthreads();
    if (tid < 8) {
        int v = s_wtot[tid];
        int ip = v;
        #pragma unroll
        for (int off = 1; off < 8; off <<= 1) {
            int t = __shfl_up_sync(0xffu, ip, off);
            if (tid >= off) ip += t;
        }
        s_woff[tid] = ip - v;
        if (tid == 7) s_n = ip;
    }
    __syncthreads();
    int wr = s_woff[warp] + pre - cnt;
    #pragma unroll
    for (int j = 0; j < 32; j++) {
        if (u.b[j] == h) {
            if (wr < MAXPH) g_rows[h * MAXPH + wr] = tid * 32 + j;
            wr++;
        }
    }
    if (tid == 0) g_cnt[h] = (s_n < MAXPH) ? s_n : MAXPH;
}

// ---------------------------------------------------------------------------
// Main: grid = 64 heads x 2 M-tiles = 128 CTAs x 256 thr.
// Stage Ah/Al (gathered x, bf16 split) + Bh/Bl (W rows, bf16 split) in SMEM;
// 3 precision passes of m16n8k16 bf16 mma.sync (HMMA tensor path, compiles
// on plain compute_103); epilogue adds bias and scatters rows.
// ---------------------------------------------------------------------------
__global__ void __launch_bounds__(THREADS) lm_mma(
    const float* __restrict__ x, const float* __restrict__ wgt,
    const float* __restrict__ bias, float* __restrict__ out)
{
    extern __shared__ __align__(16) unsigned char smem[];

    const int tid = threadIdx.x, wid = tid >> 5, lane = tid & 31;
    const int h  = blockIdx.x >> 1;
    const int m0 = (blockIdx.x & 1) * 128;

    const int n = g_cnt[h];
    if (m0 >= n) return;
    const int nm = (n - m0 < 128) ? (n - m0) : 128;
    const int* rl = g_rows + h * MAXPH + m0;

    // --- Stage B = W[h] (already [K][N] row-major), bf16 hi/lo split.
    //     thread: k = tid>>1, n-half = (tid&1)*64; packed 4B STS. ---
    {
        const int k = tid >> 1, nh0 = (tid & 1) * 64;
        const float* wr = wgt + (size_t)h * NF * NF + (size_t)k * NF + nh0;
        unsigned* bh = (unsigned*)(smem + OFF_BH) + (k * BSTRIDE + nh0) / 2;
        unsigned* bl = (unsigned*)(smem + OFF_BL) + (k * BSTRIDE + nh0) / 2;
        #pragma unroll 8
        for (int j = 0; j < 32; j++) {
            float f0 = wr[2 * j], f1 = wr[2 * j + 1];
            __nv_bfloat16 h0 = __float2bfloat16(f0);
            __nv_bfloat16 h1 = __float2bfloat16(f1);
            bh[j] = pack2(h0, h1);
            bl[j] = pack2(__float2bfloat16(f0 - __bfloat162float(h0)),
                          __float2bfloat16(f1 - __bfloat162float(h1)));
        }
    }

    // --- Stage A = gathered x rows, bf16 hi/lo split; zero-pad rows >= nm ---
    {
        const int m = tid >> 1, kh = (tid & 1) * 64;
        const bool valid = (m < nm);
        const float* xr = x + (size_t)(valid ? rl[m] : 0) * NF + kh;
        unsigned* ah = (unsigned*)(smem + OFF_AH) + (m * BSTRIDE + kh) / 2;
        unsigned* al = (unsigned*)(smem + OFF_AL) + (m * BSTRIDE + kh) / 2;
        #pragma unroll 8
        for (int j = 0; j < 32; j++) {
            float f0 = valid ? xr[2 * j]     : 0.f;
            float f1 = valid ? xr[2 * j + 1] : 0.f;
            __nv_bfloat16 h0 = __float2bfloat16(f0);
            __nv_bfloat16 h1 = __float2bfloat16(f1);
            ah[j] = pack2(h0, h1);
            al[j] = pack2(__float2bfloat16(f0 - __bfloat162float(h0)),
                          __float2bfloat16(f1 - __bfloat162float(h1)));
        }
    }
    __syncthreads();

    // --- MMA: warp w owns rows 16w..16w+15 x all 128 cols.
    //     Passes: (Ah,Bh), (Ah,Bl), (Al,Bh).  8 K-steps x 16 n8-blocks. ---
    float acc[16][4];
    #pragma unroll
    for (int nb = 0; nb < 16; nb++)
        #pragma unroll
        for (int q = 0; q < 4; q++) acc[nb][q] = 0.f;

    const uint32_t sb = smem_u32(smem);
    // ldmatrix lane addressing: A at row (lane&15), col-8-block (lane>>4);
    // B(trans) at k-row (lane&15), n-offset 8*(lane>>4).
    const uint32_t aLane = (uint32_t)((16 * wid + (lane & 15)) * BSTRIDE + ((lane >> 4) << 3)) * 2;
    const uint32_t bLane = (uint32_t)((lane & 15) * BSTRIDE + ((lane >> 4) << 3)) * 2;

    #pragma unroll 1
    for (int p = 0; p < 3; p++) {
        const uint32_t Ap = sb + ((p == 2) ? OFF_AL : OFF_AH) + aLane;
        const uint32_t Bp = sb + ((p == 1) ? OFF_BL : OFF_BH) + bLane;
        #pragma unroll
        for (int kk = 0; kk < 8; kk++) {
            uint32_t a0, a1, a2, a3;
            LDSM_X4(a0, a1, a2, a3, Ap + kk * 32);            // +16 bf16 cols
            const uint32_t Bk = Bp + kk * (16 * BSTRIDE * 2); // +16 k rows
            #pragma unroll
            for (int nb2 = 0; nb2 < 8; nb2++) {
                uint32_t b0, b1, b2, b3;
                LDSM_X4T(b0, b1, b2, b3, Bk + nb2 * 32);      // +16 n cols
                mma_bf16(acc[2 * nb2],     a0, a1, a2, a3, b0, b1);
                mma_bf16(acc[2 * nb2 + 1], a0, a1, a2, a3, b2, b3);
            }
        }
    }

    // --- Epilogue: fragment (qid,tc) -> rows 16w+qid, +8; cols nb*8+tc*2 ---
    {
        const int qid = lane >> 2, tc = lane & 3;
        const int mr0 = 16 * wid + qid, mr1 = mr0 + 8;
        const int gr0 = (mr0 < nm) ? rl[mr0] : -1;
        const int gr1 = (mr1 < nm) ? rl[mr1] : -1;
        const float* bp = bias + h * NF;
        #pragma unroll
        for (int nb = 0; nb < 16; nb++) {
            const int col = nb * 8 + tc * 2;
            const float2 bv = *reinterpret_cast<const float2*>(bp + col);
            if (gr0 >= 0) {
                float2 v = {acc[nb][0] + bv.x, acc[nb][1] + bv.y};
                *reinterpret_cast<float2*>(out + (size_t)gr0 * NF + col) = v;
            }
            if (gr1 >= 0) {
                float2 v = {acc[nb][2] + bv.x, acc[nb][3] + bv.y};
                *reinterpret_cast<float2*>(out + (size_t)gr1 * NF + col) = v;
            }
        }
    }
}

extern "C" void kernel_launch(void* const* d_in, const int* in_sizes, int n_in,
                              void* d_out, int out_size) {
    const float* x   = (const float*)d_in[0];
    const float* w   = (const float*)d_in[1];
    const float* b   = (const float*)d_in[2];
    const void*  hx  = d_in[3];   // int64 or int32, detected on-device
    float*       out = (float*)d_out;

    cudaFuncSetAttribute(lm_mma, cudaFuncAttributeMaxDynamicSharedMemorySize, SMEM_BYTES);

    lm_prep<<<NH, THREADS>>>(hx);
    lm_mma<<<NH * 2, THREADS, SMEM_BYTES>>>(x, w, b, out);
}

// round 14
// speedup vs baseline: 1.5854x; 1.5854x over previous
#include <cuda_runtime.h>
#include <cuda_bf16.h>
#include <cstdint>

#define BATCH   8192
#define NF      128
#define NH      64
#define THREADS 256
#define MAXPH   256

#define BSTRIDE 136                        // bf16 elems per smem row (272B, ldmatrix conflict-free)
#define ROWB    (BSTRIDE * 2)              // 272
#define ATILE_B (64 * ROWB)                // 17408
#define BTILE_B (128 * ROWB)               // 34816
#define OFF_AH  0
#define OFF_AL  (ATILE_B)
#define OFF_BH  (2 * ATILE_B)
#define OFF_BL  (2 * ATILE_B + BTILE_B)
#define SMEM_BYTES (2 * ATILE_B + 2 * BTILE_B)   // 104448 -> 2 CTAs/SM

__device__ int g_rows[NH * MAXPH];
__device__ int g_cnt[NH];
__device__ __align__(16) __nv_bfloat16 g_wh[NH * NF * NF];
__device__ __align__(16) __nv_bfloat16 g_wl[NH * NF * NF];
__device__ __align__(16) __nv_bfloat16 g_xh[BATCH * NF];
__device__ __align__(16) __nv_bfloat16 g_xl[BATCH * NF];

__device__ __forceinline__ uint32_t smem_u32(const void* p) {
    return (uint32_t)__cvta_generic_to_shared(p);
}
__device__ __forceinline__ unsigned pack2(__nv_bfloat16 a, __nv_bfloat16 b) {
    return (unsigned)__bfloat16_as_ushort(a) | ((unsigned)__bfloat16_as_ushort(b) << 16);
}

#define LDSM_X4(r0, r1, r2, r3, addr) \
    asm volatile("ldmatrix.sync.aligned.m8n8.x4.shared.b16 {%0,%1,%2,%3}, [%4];" \
                 : "=r"(r0), "=r"(r1), "=r"(r2), "=r"(r3) : "r"(addr))
#define LDSM_X4T(r0, r1, r2, r3, addr) \
    asm volatile("ldmatrix.sync.aligned.m8n8.x4.trans.shared.b16 {%0,%1,%2,%3}, [%4];" \
                 : "=r"(r0), "=r"(r1), "=r"(r2), "=r"(r3) : "r"(addr))

__device__ __forceinline__ void mma_bf16(float* c,
    uint32_t a0, uint32_t a1, uint32_t a2, uint32_t a3, uint32_t b0, uint32_t b1) {
    asm volatile(
        "mma.sync.aligned.m16n8k16.row.col.f32.bf16.bf16.f32 "
        "{%0,%1,%2,%3}, {%4,%5,%6,%7}, {%8,%9}, {%0,%1,%2,%3};"
        : "+f"(c[0]), "+f"(c[1]), "+f"(c[2]), "+f"(c[3])
        : "r"(a0), "r"(a1), "r"(a2), "r"(a3), "r"(b0), "r"(b1));
}

// ---------------------------------------------------------------------------
// Conv: grid-wide coalesced bf16 hi/lo split of W and x into device globals.
// 2048 CTAs x 256 thr, one float4 per thread.
// ---------------------------------------------------------------------------
__global__ void __launch_bounds__(THREADS) lm_conv(
    const float* __restrict__ x, const float* __restrict__ wgt)
{
    const int WF4 = NH * NF * NF / 4;
    int i = blockIdx.x * THREADS + threadIdx.x;
    float4 v;
    __nv_bfloat16 *dh, *dl;
    if (i < WF4) {
        v = reinterpret_cast<const float4*>(wgt)[i];
        dh = g_wh + 4 * (size_t)i;  dl = g_wl + 4 * (size_t)i;
    } else {
        int j = i - WF4;
        v = reinterpret_cast<const float4*>(x)[j];
        dh = g_xh + 4 * (size_t)j;  dl = g_xl + 4 * (size_t)j;
    }
    __nv_bfloat16 h0 = __float2bfloat16(v.x), h1 = __float2bfloat16(v.y);
    __nv_bfloat16 h2 = __float2bfloat16(v.z), h3 = __float2bfloat16(v.w);
    uint2 ph = { pack2(h0, h1), pack2(h2, h3) };
    uint2 pl = { pack2(__float2bfloat16(v.x - __bfloat162float(h0)),
                       __float2bfloat16(v.y - __bfloat162float(h1))),
                 pack2(__float2bfloat16(v.z - __bfloat162float(h2)),
                       __float2bfloat16(v.w - __bfloat162float(h3))) };
    *reinterpret_cast<uint2*>(dh) = ph;
    *reinterpret_cast<uint2*>(dl) = pl;
}

// ---------------------------------------------------------------------------
// Prep (validated R10-R13): one CTA per head; dtype-detect head_ix, build
// ordered per-head row lists in g_rows/g_cnt.
// ---------------------------------------------------------------------------
__global__ void __launch_bounds__(THREADS) lm_prep(const void* __restrict__ hx) {
    __shared__ int s_wtot[8], s_woff[8], s_n;
    const int tid = threadIdx.x, warp = tid >> 5, lane = tid & 31;
    const int h = blockIdx.x;

    const unsigned* wd = (const unsigned*)hx;
    unsigned a = 0;
    #pragma unroll
    for (int m = 0; m < 8; m++) a |= wd[2 * (tid + m * THREADS) + 1];
    const int is32 = __syncthreads_or(a != 0);

    union { unsigned v[8]; unsigned char b[32]; } u;
    if (is32) {
        const int4* p = (const int4*)hx;
        #pragma unroll
        for (int j = 0; j < 8; j++) {
            int4 q = p[tid * 8 + j];
            u.v[j] = (unsigned)q.x | ((unsigned)q.y << 8) |
                     ((unsigned)q.z << 16) | ((unsigned)q.w << 24);
        }
    } else {
        const ulonglong2* p = (const ulonglong2*)hx;
        #pragma unroll
        for (int j = 0; j < 8; j++) {
            ulonglong2 q0 = p[tid * 16 + 2 * j];
            ulonglong2 q1 = p[tid * 16 + 2 * j + 1];
            u.v[j] = (unsigned)(q0.x & 0xff) | ((unsigned)(q0.y & 0xff) << 8) |
                     ((unsigned)(q1.x & 0xff) << 16) | ((unsigned)(q1.y & 0xff) << 24);
        }
    }

    int cnt = 0;
    #pragma unroll
    for (int j = 0; j < 32; j++) cnt += (u.b[j] == h);
    int pre = cnt;
    #pragma unroll
    for (int off = 1; off < 32; off <<= 1) {
        int t = __shfl_up_sync(~0u, pre, off);
        if (lane >= off) pre += t;
    }
    if (lane == 31) s_wtot[warp] = pre;
    __syncthreads();
    if (tid < 8) {
        int v = s_wtot[tid];
        int ip = v;
        #pragma unroll
        for (int off = 1; off < 8; off <<= 1) {
            int t = __shfl_up_sync(0xffu, ip, off);
            if (tid >= off) ip += t;
        }
        s_woff[tid] = ip - v;
        if (tid == 7) s_n = ip;
    }
    __syncthreads();
    int wr = s_woff[warp] + pre - cnt;
    #pragma unroll
    for (int j = 0; j < 32; j++) {
        if (u.b[j] == h) {
            if (wr < MAXPH) g_rows[h * MAXPH + wr] = tid * 32 + j;
            wr++;
        }
    }
    if (tid == 0) g_cnt[h] = (s_n < MAXPH) ? s_n : MAXPH;
}

// ---------------------------------------------------------------------------
// Main: grid = 64 heads x 4 M-slices(64 rows) = 256 CTAs x 256 thr, 2/SM.
// Stage pre-converted bf16 tiles (pure uint4 copies), 3-pass m16n8k16
// mma.sync (validated R13 recipe; warp = rowg x colhalf), bias + scatter.
// ---------------------------------------------------------------------------
__global__ void __launch_bounds__(THREADS, 2) lm_mma(
    const float* __restrict__ bias, float* __restrict__ out)
{
    extern __shared__ __align__(16) unsigned char smem[];

    const int tid = threadIdx.x, wid = tid >> 5, lane = tid & 31;
    const int h  = blockIdx.x >> 2;
    const int m0 = (blockIdx.x & 3) * 64;

    const int n = g_cnt[h];
    if (m0 >= n) return;
    const int nm = (n - m0 < 64) ? (n - m0) : 64;
    const int* rl = g_rows + h * MAXPH + m0;

    // --- Stage B (128x128 bf16, hi+lo): 8 uint4/thread per tile ---
    {
        const uint4* sh = reinterpret_cast<const uint4*>(g_wh + (size_t)h * NF * NF);
        const uint4* sl = reinterpret_cast<const uint4*>(g_wl + (size_t)h * NF * NF);
        #pragma unroll
        for (int q = 0; q < 8; q++) {
            int idx = q * THREADS + tid;          // 0..2047 (uint4 units)
            int row = idx >> 4, c = idx & 15;
            uint32_t off = row * ROWB + c * 16;
            *reinterpret_cast<uint4*>(smem + OFF_BH + off) = sh[idx];
            *reinterpret_cast<uint4*>(smem + OFF_BL + off) = sl[idx];
        }
    }
    // --- Stage A (64 gathered x rows, hi+lo): 4 uint4/thread per tile ---
    {
        #pragma unroll
        for (int q = 0; q < 4; q++) {
            int idx = q * THREADS + tid;          // 0..1023
            int row = idx >> 4, c = idx & 15;
            const bool valid = (row < nm);
            const size_t gb = (size_t)(valid ? rl[row] : 0) * NF;
            uint4 vh = {0, 0, 0, 0}, vl = {0, 0, 0, 0};
            if (valid) {
                vh = reinterpret_cast<const uint4*>(g_xh + gb)[c];
                vl = reinterpret_cast<const uint4*>(g_xl + gb)[c];
            }
            uint32_t off = row * ROWB + c * 16;
            *reinterpret_cast<uint4*>(smem + OFF_AH + off) = vh;
            *reinterpret_cast<uint4*>(smem + OFF_AL + off) = vl;
        }
    }
    __syncthreads();

    // --- MMA: warp = (rowg 0..3)x(ch 0..1): rows 16*rowg.., cols ch*64.. ---
    const int rowg = wid >> 1, ch = wid & 1;
    float acc[8][4];
    #pragma unroll
    for (int nb = 0; nb < 8; nb++)
        #pragma unroll
        for (int q = 0; q < 4; q++) acc[nb][q] = 0.f;

    const uint32_t sb = smem_u32(smem);
    const uint32_t aLane = (uint32_t)((16 * rowg + (lane & 15)) * ROWB + ((lane >> 4) << 4));
    const uint32_t bLane = (uint32_t)((lane & 15) * ROWB + ch * 128 + ((lane >> 4) << 4));

    #pragma unroll 1
    for (int p = 0; p < 3; p++) {
        const uint32_t Ap = sb + ((p == 2) ? OFF_AL : OFF_AH) + aLane;
        const uint32_t Bp = sb + ((p == 1) ? OFF_BL : OFF_BH) + bLane;
        #pragma unroll
        for (int kk = 0; kk < 8; kk++) {
            uint32_t a0, a1, a2, a3;
            LDSM_X4(a0, a1, a2, a3, Ap + kk * 32);            // +16 bf16 k-cols
            const uint32_t Bk = Bp + kk * (16 * ROWB);        // +16 k-rows
            #pragma unroll
            for (int nb2 = 0; nb2 < 4; nb2++) {
                uint32_t b0, b1, b2, b3;
                LDSM_X4T(b0, b1, b2, b3, Bk + nb2 * 32);      // +16 n-cols
                mma_bf16(acc[2 * nb2],     a0, a1, a2, a3, b0, b1);
                mma_bf16(acc[2 * nb2 + 1], a0, a1, a2, a3, b2, b3);
            }
        }
    }

    // --- Epilogue: fragment (qid,tc) -> rows 16*rowg+qid, +8; col ch*64+nb*8+tc*2 ---
    {
        const int qid = lane >> 2, tc = lane & 3;
        const int mr0 = 16 * rowg + qid, mr1 = mr0 + 8;
        const int gr0 = (mr0 < nm) ? rl[mr0] : -1;
        const int gr1 = (mr1 < nm) ? rl[mr1] : -1;
        const float* bp = bias + h * NF + ch * 64;
        #pragma unroll
        for (int nb = 0; nb < 8; nb++) {
            const int col = nb * 8 + tc * 2;
            const float2 bv = *reinterpret_cast<const float2*>(bp + col);
            const int ocol = ch * 64 + col;
            if (gr0 >= 0) {
                float2 v = {acc[nb][0] + bv.x, acc[nb][1] + bv.y};
                *reinterpret_cast<float2*>(out + (size_t)gr0 * NF + ocol) = v;
            }
            if (gr1 >= 0) {
                float2 v = {acc[nb][2] + bv.x, acc[nb][3] + bv.y};
                *reinterpret_cast<float2*>(out + (size_t)gr1 * NF + ocol) = v;
            }
        }
    }
}

extern "C" void kernel_launch(void* const* d_in, const int* in_sizes, int n_in,
                              void* d_out, int out_size) {
    const float* x   = (const float*)d_in[0];
    const float* w   = (const float*)d_in[1];
    const float* b   = (const float*)d_in[2];
    const void*  hx  = d_in[3];   // int64 or int32, detected on-device
    float*       out = (float*)d_out;

    cudaFuncSetAttribute(lm_mma, cudaFuncAttributeMaxDynamicSharedMemorySize, SMEM_BYTES);

    const int CONV_CTAS = (NH * NF * NF / 4 + BATCH * NF / 4) / THREADS;  // 2048
    lm_conv<<<CONV_CTAS, THREADS>>>(x, w);
    lm_prep<<<NH, THREADS>>>(hx);
    lm_mma<<<NH * 4, THREADS, SMEM_BYTES>>>(b, out);
}

// round 15
// speedup vs baseline: 1.9734x; 1.2448x over previous
#include <cuda_runtime.h>
#include <cuda_bf16.h>
#include <cstdint>

#define BATCH   8192
#define NF      128
#define NH      64
#define THREADS 256
#define MAXPH   256

#define BSTRIDE 136                        // bf16 elems per smem row (272B)
#define ROWB    (BSTRIDE * 2)              // 272
#define ATILE_B (64 * ROWB)                // 17408
#define BTILE_B (128 * ROWB)               // 34816
#define OFF_AH  0
#define OFF_AL  (ATILE_B)
#define OFF_BH  (2 * ATILE_B)
#define OFF_BL  (2 * ATILE_B + BTILE_B)
#define SMEM_BYTES (2 * ATILE_B + 2 * BTILE_B)   // 104448 -> 2 CTAs/SM

__device__ int g_rows[NH * MAXPH];
__device__ int g_cnt[NH];

__device__ __forceinline__ uint32_t smem_u32(const void* p) {
    return (uint32_t)__cvta_generic_to_shared(p);
}
__device__ __forceinline__ unsigned pack2(__nv_bfloat16 a, __nv_bfloat16 b) {
    return (unsigned)__bfloat16_as_ushort(a) | ((unsigned)__bfloat16_as_ushort(b) << 16);
}
// split float4 -> packed bf16 hi (8B) and lo (8B)
__device__ __forceinline__ void split4(float4 v, uint2& ph, uint2& pl) {
    __nv_bfloat16 h0 = __float2bfloat16(v.x), h1 = __float2bfloat16(v.y);
    __nv_bfloat16 h2 = __float2bfloat16(v.z), h3 = __float2bfloat16(v.w);
    ph.x = pack2(h0, h1);  ph.y = pack2(h2, h3);
    pl.x = pack2(__float2bfloat16(v.x - __bfloat162float(h0)),
                 __float2bfloat16(v.y - __bfloat162float(h1)));
    pl.y = pack2(__float2bfloat16(v.z - __bfloat162float(h2)),
                 __float2bfloat16(v.w - __bfloat162float(h3)));
}

#define LDSM_X4(r0, r1, r2, r3, addr) \
    asm volatile("ldmatrix.sync.aligned.m8n8.x4.shared.b16 {%0,%1,%2,%3}, [%4];" \
                 : "=r"(r0), "=r"(r1), "=r"(r2), "=r"(r3) : "r"(addr))
#define LDSM_X4T(r0, r1, r2, r3, addr) \
    asm volatile("ldmatrix.sync.aligned.m8n8.x4.trans.shared.b16 {%0,%1,%2,%3}, [%4];" \
                 : "=r"(r0), "=r"(r1), "=r"(r2), "=r"(r3) : "r"(addr))

__device__ __forceinline__ void mma_bf16(float* c,
    uint32_t a0, uint32_t a1, uint32_t a2, uint32_t a3, uint32_t b0, uint32_t b1) {
    asm volatile(
        "mma.sync.aligned.m16n8k16.row.col.f32.bf16.bf16.f32 "
        "{%0,%1,%2,%3}, {%4,%5,%6,%7}, {%8,%9}, {%0,%1,%2,%3};"
        : "+f"(c[0]), "+f"(c[1]), "+f"(c[2]), "+f"(c[3])
        : "r"(a0), "r"(a1), "r"(a2), "r"(a3), "r"(b0), "r"(b1));
}

// ---------------------------------------------------------------------------
// Prep (validated R10-R14): one CTA per head; dtype-detect head_ix, build
// ordered per-head row lists in g_rows/g_cnt.
// ---------------------------------------------------------------------------
__global__ void __launch_bounds__(THREADS) lm_prep(const void* __restrict__ hx) {
    __shared__ int s_wtot[8], s_woff[8], s_n;
    const int tid = threadIdx.x, warp = tid >> 5, lane = tid & 31;
    const int h = blockIdx.x;

    const unsigned* wd = (const unsigned*)hx;
    unsigned a = 0;
    #pragma unroll
    for (int m = 0; m < 8; m++) a |= wd[2 * (tid + m * THREADS) + 1];
    const int is32 = __syncthreads_or(a != 0);

    union { unsigned v[8]; unsigned char b[32]; } u;
    if (is32) {
        const int4* p = (const int4*)hx;
        #pragma unroll
        for (int j = 0; j < 8; j++) {
            int4 q = p[tid * 8 + j];
            u.v[j] = (unsigned)q.x | ((unsigned)q.y << 8) |
                     ((unsigned)q.z << 16) | ((unsigned)q.w << 24);
        }
    } else {
        const ulonglong2* p = (const ulonglong2*)hx;
        #pragma unroll
        for (int j = 0; j < 8; j++) {
            ulonglong2 q0 = p[tid * 16 + 2 * j];
            ulonglong2 q1 = p[tid * 16 + 2 * j + 1];
            u.v[j] = (unsigned)(q0.x & 0xff) | ((unsigned)(q0.y & 0xff) << 8) |
                     ((unsigned)(q1.x & 0xff) << 16) | ((unsigned)(q1.y & 0xff) << 24);
        }
    }

    int cnt = 0;
    #pragma unroll
    for (int j = 0; j < 32; j++) cnt += (u.b[j] == h);
    int pre = cnt;
    #pragma unroll
    for (int off = 1; off < 32; off <<= 1) {
        int t = __shfl_up_sync(~0u, pre, off);
        if (lane >= off) pre += t;
    }
    if (lane == 31) s_wtot[warp] = pre;
    __syncthreads();
    if (tid < 8) {
        int v = s_wtot[tid];
        int ip = v;
        #pragma unroll
        for (int off = 1; off < 8; off <<= 1) {
            int t = __shfl_up_sync(0xffu, ip, off);
            if (tid >= off) ip += t;
        }
        s_woff[tid] = ip - v;
        if (tid == 7) s_n = ip;
    }
    __syncthreads();
    int wr = s_woff[warp] + pre - cnt;
    #pragma unroll
    for (int j = 0; j < 32; j++) {
        if (u.b[j] == h) {
            if (wr < MAXPH) g_rows[h * MAXPH + wr] = tid * 32 + j;
            wr++;
        }
    }
    if (tid == 0) g_cnt[h] = (s_n < MAXPH) ? s_n : MAXPH;
}

// ---------------------------------------------------------------------------
// Main: grid = 64 heads x 4 M-slices(64 rows) = 256 CTAs x 256 thr, 2/SM.
// In-CTA bf16 hi/lo conversion of W and gathered x (coalesced float4 LDG,
// conflict-free STS.64), then 3-precision-pass m16n8k16 mma.sync with A
// fragments hoisted across passes; bias + scatter epilogue.
// ---------------------------------------------------------------------------
__global__ void __launch_bounds__(THREADS, 2) lm_mma(
    const float* __restrict__ x, const float* __restrict__ wgt,
    const float* __restrict__ bias, float* __restrict__ out)
{
    extern __shared__ __align__(16) unsigned char smem[];

    const int tid = threadIdx.x, wid = tid >> 5, lane = tid & 31;
    const int h  = blockIdx.x >> 2;
    const int m0 = (blockIdx.x & 3) * 64;

    const int n = g_cnt[h];
    if (m0 >= n) return;
    const int nm = (n - m0 < 64) ? (n - m0) : 64;
    const int* rl = g_rows + h * MAXPH + m0;

    // --- Stage B = W[h] with fused bf16 split.  Warp covers one 128-float
    //     row per step (lane = float4 within row); STS.64 stride 8B. ---
    {
        const float4* wf = reinterpret_cast<const float4*>(wgt + (size_t)h * NF * NF);
        #pragma unroll
        for (int q = 0; q < 16; q++) {
            int idx = q * THREADS + tid;          // 0..4095 float4s
            int row = idx >> 5, c4 = idx & 31;
            float4 v = wf[idx];
            uint2 ph, pl;
            split4(v, ph, pl);
            uint32_t off = row * ROWB + c4 * 8;
            *reinterpret_cast<uint2*>(smem + OFF_BH + off) = ph;
            *reinterpret_cast<uint2*>(smem + OFF_BL + off) = pl;
        }
    }
    // --- Stage A = gathered x rows with fused bf16 split; zero-pad ---
    {
        #pragma unroll
        for (int q = 0; q < 8; q++) {
            int idx = q * THREADS + tid;          // 0..2047 float4s
            int row = idx >> 5, c4 = idx & 31;
            const bool valid = (row < nm);
            float4 v = {0.f, 0.f, 0.f, 0.f};
            if (valid)
                v = reinterpret_cast<const float4*>(x + (size_t)rl[row] * NF)[c4];
            uint2 ph, pl;
            split4(v, ph, pl);
            uint32_t off = row * ROWB + c4 * 8;
            *reinterpret_cast<uint2*>(smem + OFF_AH + off) = ph;
            *reinterpret_cast<uint2*>(smem + OFF_AL + off) = pl;
        }
    }
    __syncthreads();

    // --- MMA: warp = (rowg 0..3) x (ch 0..1).  Per kk: load Ah+Al frags once,
    //     stream Bh (mma vs Ah and Al) then Bl (mma vs Ah).  272 ops/warp. ---
    const int rowg = wid >> 1, ch = wid & 1;
    float acc[8][4];
    #pragma unroll
    for (int nb = 0; nb < 8; nb++)
        #pragma unroll
        for (int q = 0; q < 4; q++) acc[nb][q] = 0.f;

    const uint32_t sb = smem_u32(smem);
    const uint32_t aLane = (uint32_t)((16 * rowg + (lane & 15)) * ROWB + ((lane >> 4) << 4));
    const uint32_t bLane = (uint32_t)((lane & 15) * ROWB + ch * 128 + ((lane >> 4) << 4));

    #pragma unroll
    for (int kk = 0; kk < 8; kk++) {
        uint32_t ah0, ah1, ah2, ah3, al0, al1, al2, al3;
        LDSM_X4(ah0, ah1, ah2, ah3, sb + OFF_AH + aLane + kk * 32);
        LDSM_X4(al0, al1, al2, al3, sb + OFF_AL + aLane + kk * 32);
        const uint32_t BkH = sb + OFF_BH + bLane + kk * (16 * ROWB);
        const uint32_t BkL = sb + OFF_BL + bLane + kk * (16 * ROWB);
        #pragma unroll
        for (int nb2 = 0; nb2 < 4; nb2++) {
            uint32_t b0, b1, b2, b3;
            LDSM_X4T(b0, b1, b2, b3, BkH + nb2 * 32);
            mma_bf16(acc[2 * nb2],     ah0, ah1, ah2, ah3, b0, b1);
            mma_bf16(acc[2 * nb2 + 1], ah0, ah1, ah2, ah3, b2, b3);
            mma_bf16(acc[2 * nb2],     al0, al1, al2, al3, b0, b1);
            mma_bf16(acc[2 * nb2 + 1], al0, al1, al2, al3, b2, b3);
        }
        #pragma unroll
        for (int nb2 = 0; nb2 < 4; nb2++) {
            uint32_t b0, b1, b2, b3;
            LDSM_X4T(b0, b1, b2, b3, BkL + nb2 * 32);
            mma_bf16(acc[2 * nb2],     ah0, ah1, ah2, ah3, b0, b1);
            mma_bf16(acc[2 * nb2 + 1], ah0, ah1, ah2, ah3, b2, b3);
        }
    }

    // --- Epilogue (validated R13/R14): fragment (qid,tc) -> rows 16*rowg+qid,
    //     +8; col ch*64 + nb*8 + tc*2 ---
    {
        const int qid = lane >> 2, tc = lane & 3;
        const int mr0 = 16 * rowg + qid, mr1 = mr0 + 8;
        const int gr0 = (mr0 < nm) ? rl[mr0] : -1;
        const int gr1 = (mr1 < nm) ? rl[mr1] : -1;
        const float* bp = bias + h * NF + ch * 64;
        #pragma unroll
        for (int nb = 0; nb < 8; nb++) {
            const int col = nb * 8 + tc * 2;
            const float2 bv = *reinterpret_cast<const float2*>(bp + col);
            const int ocol = ch * 64 + col;
            if (gr0 >= 0) {
                float2 v = {acc[nb][0] + bv.x, acc[nb][1] + bv.y};
                *reinterpret_cast<float2*>(out + (size_t)gr0 * NF + ocol) = v;
            }
            if (gr1 >= 0) {
                float2 v = {acc[nb][2] + bv.x, acc[nb][3] + bv.y};
                *reinterpret_cast<float2*>(out + (size_t)gr1 * NF + ocol) = v;
            }
        }
    }
}

extern "C" void kernel_launch(void* const* d_in, const int* in_sizes, int n_in,
                              void* d_out, int out_size) {
    const float* x   = (const float*)d_in[0];
    const float* w   = (const float*)d_in[1];
    const float* b   = (const float*)d_in[2];
    const void*  hx  = d_in[3];   // int64 or int32, detected on-device
    float*       out = (float*)d_out;

    cudaFuncSetAttribute(lm_mma, cudaFuncAttributeMaxDynamicSharedMemorySize, SMEM_BYTES);

    lm_prep<<<NH, THREADS>>>(hx);
    lm_mma<<<NH * 4, THREADS, SMEM_BYTES>>>(x, w, b, out);
}

// round 16
// speedup vs baseline: 2.2462x; 1.1382x over previous
#include <cuda_runtime.h>
#include <cuda_bf16.h>
#include <cstdint>

#define BATCH   8192
#define NF      128
#define NH      64
#define THREADS 256
#define MAXPH   256

#define AROWB   272                        // A smem row bytes (136 bf16)
#define BROWB   144                        // B smem row bytes (72 bf16)
#define ATILE_B (64 * AROWB)               // 17408
#define BTILE_B (128 * BROWB)              // 18432
#define OFF_AH  0
#define OFF_AL  (ATILE_B)
#define OFF_BH  (2 * ATILE_B)
#define OFF_BL  (2 * ATILE_B + BTILE_B)
#define SMEM_BYTES (2 * ATILE_B + 2 * BTILE_B)   // 71680 -> 3 CTAs/SM

__device__ int g_rows[NH * MAXPH];
__device__ int g_cnt[NH];

__device__ __forceinline__ uint32_t smem_u32(const void* p) {
    return (uint32_t)__cvta_generic_to_shared(p);
}
// cheap bf16 hi/lo split: hi = truncation (prmt pack), lo = rn(residual)
__device__ __forceinline__ void split4(float4 v, uint2& ph, uint2& pl) {
    unsigned u0 = __float_as_uint(v.x), u1 = __float_as_uint(v.y);
    unsigned u2 = __float_as_uint(v.z), u3 = __float_as_uint(v.w);
    asm("prmt.b32 %0, %1, %2, 0x7632;" : "=r"(ph.x) : "r"(u0), "r"(u1));
    asm("prmt.b32 %0, %1, %2, 0x7632;" : "=r"(ph.y) : "r"(u2), "r"(u3));
    float r0 = v.x - __uint_as_float(u0 & 0xffff0000u);
    float r1 = v.y - __uint_as_float(u1 & 0xffff0000u);
    float r2 = v.z - __uint_as_float(u2 & 0xffff0000u);
    float r3 = v.w - __uint_as_float(u3 & 0xffff0000u);
    asm("cvt.rn.bf16x2.f32 %0, %1, %2;" : "=r"(pl.x) : "f"(r1), "f"(r0));
    asm("cvt.rn.bf16x2.f32 %0, %1, %2;" : "=r"(pl.y) : "f"(r3), "f"(r2));
}

#define LDSM_X4(r0, r1, r2, r3, addr) \
    asm volatile("ldmatrix.sync.aligned.m8n8.x4.shared.b16 {%0,%1,%2,%3}, [%4];" \
                 : "=r"(r0), "=r"(r1), "=r"(r2), "=r"(r3) : "r"(addr))
#define LDSM_X4T(r0, r1, r2, r3, addr) \
    asm volatile("ldmatrix.sync.aligned.m8n8.x4.trans.shared.b16 {%0,%1,%2,%3}, [%4];" \
                 : "=r"(r0), "=r"(r1), "=r"(r2), "=r"(r3) : "r"(addr))

__device__ __forceinline__ void mma_bf16(float* c,
    uint32_t a0, uint32_t a1, uint32_t a2, uint32_t a3, uint32_t b0, uint32_t b1) {
    asm volatile(
        "mma.sync.aligned.m16n8k16.row.col.f32.bf16.bf16.f32 "
        "{%0,%1,%2,%3}, {%4,%5,%6,%7}, {%8,%9}, {%0,%1,%2,%3};"
        : "+f"(c[0]), "+f"(c[1]), "+f"(c[2]), "+f"(c[3])
        : "r"(a0), "r"(a1), "r"(a2), "r"(a3), "r"(b0), "r"(b1));
}

// ---------------------------------------------------------------------------
// Prep (validated R10-R15): one CTA per head; dtype-detect head_ix, build
// ordered per-head row lists in g_rows/g_cnt.
// ---------------------------------------------------------------------------
__global__ void __launch_bounds__(THREADS) lm_prep(const void* __restrict__ hx) {
    __shared__ int s_wtot[8], s_woff[8], s_n;
    const int tid = threadIdx.x, warp = tid >> 5, lane = tid & 31;
    const int h = blockIdx.x;

    const unsigned* wd = (const unsigned*)hx;
    unsigned a = 0;
    #pragma unroll
    for (int m = 0; m < 8; m++) a |= wd[2 * (tid + m * THREADS) + 1];
    const int is32 = __syncthreads_or(a != 0);

    union { unsigned v[8]; unsigned char b[32]; } u;
    if (is32) {
        const int4* p = (const int4*)hx;
        #pragma unroll
        for (int j = 0; j < 8; j++) {
            int4 q = p[tid * 8 + j];
            u.v[j] = (unsigned)q.x | ((unsigned)q.y << 8) |
                     ((unsigned)q.z << 16) | ((unsigned)q.w << 24);
        }
    } else {
        const ulonglong2* p = (const ulonglong2*)hx;
        #pragma unroll
        for (int j = 0; j < 8; j++) {
            ulonglong2 q0 = p[tid * 16 + 2 * j];
            ulonglong2 q1 = p[tid * 16 + 2 * j + 1];
            u.v[j] = (unsigned)(q0.x & 0xff) | ((unsigned)(q0.y & 0xff) << 8) |
                     ((unsigned)(q1.x & 0xff) << 16) | ((unsigned)(q1.y & 0xff) << 24);
        }
    }

    int cnt = 0;
    #pragma unroll
    for (int j = 0; j < 32; j++) cnt += (u.b[j] == h);
    int pre = cnt;
    #pragma unroll
    for (int off = 1; off < 32; off <<= 1) {
        int t = __shfl_up_sync(~0u, pre, off);
        if (lane >= off) pre += t;
    }
    if (lane == 31) s_wtot[warp] = pre;
    __syncthreads();
    if (tid < 8) {
        int v = s_wtot[tid];
        int ip = v;
        #pragma unroll
        for (int off = 1; off < 8; off <<= 1) {
            int t = __shfl_up_sync(0xffu, ip, off);
            if (tid >= off) ip += t;
        }
        s_woff[tid] = ip - v;
        if (tid == 7) s_n = ip;
    }
    __syncthreads();
    int wr = s_woff[warp] + pre - cnt;
    #pragma unroll
    for (int j = 0; j < 32; j++) {
        if (u.b[j] == h) {
            if (wr < MAXPH) g_rows[h * MAXPH + wr] = tid * 32 + j;
            wr++;
        }
    }
    if (tid == 0) g_cnt[h] = (s_n < MAXPH) ? s_n : MAXPH;
}

// ---------------------------------------------------------------------------
// Main: grid = 64 heads x 2 N-halves x 4 M-slices = 512 CTAs x 256 thr, 3/SM.
// CTA tile 64 rows x 64 cols. Fused bf16 split staging; 3-pass m16n8k16
// mma.sync (warp = 16 rows x 32 cols); bias + scatter epilogue.
// ---------------------------------------------------------------------------
__global__ void __launch_bounds__(THREADS, 3) lm_mma(
    const float* __restrict__ x, const float* __restrict__ wgt,
    const float* __restrict__ bias, float* __restrict__ out)
{
    extern __shared__ __align__(16) unsigned char smem[];

    const int tid = threadIdx.x, wid = tid >> 5, lane = tid & 31;
    const int blk = blockIdx.x;
    const int h   = blk >> 3;
    const int nh  = (blk >> 2) & 1;       // N-half (64 cols)
    const int m0  = (blk & 3) * 64;       // M-slice

    const int n = g_cnt[h];
    if (m0 >= n) return;
    const int nm = (n - m0 < 64) ? (n - m0) : 64;
    const int* rl = g_rows + h * MAXPH + m0;

    // --- Stage B = W[h][:, nh*64..+63], fused split: 8 float4/thread ---
    {
        const float4* wf = reinterpret_cast<const float4*>(wgt + (size_t)h * NF * NF) + nh * 16;
        #pragma unroll
        for (int q = 0; q < 8; q++) {
            int idx = q * THREADS + tid;          // 0..2047
            int row = idx >> 4, c4 = idx & 15;
            float4 v = wf[row * 32 + c4];
            uint2 ph, pl;
            split4(v, ph, pl);
            uint32_t off = row * BROWB + c4 * 8;
            *reinterpret_cast<uint2*>(smem + OFF_BH + off) = ph;
            *reinterpret_cast<uint2*>(smem + OFF_BL + off) = pl;
        }
    }
    // --- Stage A = gathered x rows (full K), fused split; zero-pad ---
    {
        #pragma unroll
        for (int q = 0; q < 8; q++) {
            int idx = q * THREADS + tid;          // 0..2047
            int row = idx >> 5, c4 = idx & 31;
            const bool valid = (row < nm);
            float4 v = {0.f, 0.f, 0.f, 0.f};
            if (valid)
                v = reinterpret_cast<const float4*>(x + (size_t)rl[row] * NF)[c4];
            uint2 ph, pl;
            split4(v, ph, pl);
            uint32_t off = row * AROWB + c4 * 8;
            *reinterpret_cast<uint2*>(smem + OFF_AH + off) = ph;
            *reinterpret_cast<uint2*>(smem + OFF_AL + off) = pl;
        }
    }
    __syncthreads();

    // --- MMA: warp = (rowg 0..3) x (ch 0..1): rows 16*rowg.., cols ch*32.. ---
    const int rowg = wid >> 1, ch = wid & 1;
    float acc[4][4];
    #pragma unroll
    for (int nb = 0; nb < 4; nb++)
        #pragma unroll
        for (int q = 0; q < 4; q++) acc[nb][q] = 0.f;

    const uint32_t sb = smem_u32(smem);
    const uint32_t aLane = (uint32_t)((16 * rowg + (lane & 15)) * AROWB + ((lane >> 4) << 4));
    const uint32_t bLane = (uint32_t)((lane & 15) * BROWB + ch * 64 + ((lane >> 4) << 4));

    #pragma unroll
    for (int kk = 0; kk < 8; kk++) {
        uint32_t ah0, ah1, ah2, ah3, al0, al1, al2, al3;
        LDSM_X4(ah0, ah1, ah2, ah3, sb + OFF_AH + aLane + kk * 32);
        LDSM_X4(al0, al1, al2, al3, sb + OFF_AL + aLane + kk * 32);
        const uint32_t BkH = sb + OFF_BH + bLane + kk * (16 * BROWB);
        const uint32_t BkL = sb + OFF_BL + bLane + kk * (16 * BROWB);
        #pragma unroll
        for (int nb2 = 0; nb2 < 2; nb2++) {
            uint32_t b0, b1, b2, b3;
            LDSM_X4T(b0, b1, b2, b3, BkH + nb2 * 32);
            mma_bf16(acc[2 * nb2],     ah0, ah1, ah2, ah3, b0, b1);
            mma_bf16(acc[2 * nb2 + 1], ah0, ah1, ah2, ah3, b2, b3);
            mma_bf16(acc[2 * nb2],     al0, al1, al2, al3, b0, b1);
            mma_bf16(acc[2 * nb2 + 1], al0, al1, al2, al3, b2, b3);
        }
        #pragma unroll
        for (int nb2 = 0; nb2 < 2; nb2++) {
            uint32_t b0, b1, b2, b3;
            LDSM_X4T(b0, b1, b2, b3, BkL + nb2 * 32);
            mma_bf16(acc[2 * nb2],     ah0, ah1, ah2, ah3, b0, b1);
            mma_bf16(acc[2 * nb2 + 1], ah0, ah1, ah2, ah3, b2, b3);
        }
    }

    // --- Epilogue: fragment (qid,tc) -> rows 16*rowg+qid,+8;
    //     col nh*64 + ch*32 + nb*8 + tc*2 ---
    {
        const int qid = lane >> 2, tc = lane & 3;
        const int mr0 = 16 * rowg + qid, mr1 = mr0 + 8;
        const int gr0 = (mr0 < nm) ? rl[mr0] : -1;
        const int gr1 = (mr1 < nm) ? rl[mr1] : -1;
        const int cbase = nh * 64 + ch * 32;
        const float* bp = bias + h * NF + cbase;
        #pragma unroll
        for (int nb = 0; nb < 4; nb++) {
            const int col = nb * 8 + tc * 2;
            const float2 bv = *reinterpret_cast<const float2*>(bp + col);
            const int ocol = cbase + col;
            if (gr0 >= 0) {
                float2 v = {acc[nb][0] + bv.x, acc[nb][1] + bv.y};
                *reinterpret_cast<float2*>(out + (size_t)gr0 * NF + ocol) = v;
            }
            if (gr1 >= 0) {
                float2 v = {acc[nb][2] + bv.x, acc[nb][3] + bv.y};
                *reinterpret_cast<float2*>(out + (size_t)gr1 * NF + ocol) = v;
            }
        }
    }
}

extern "C" void kernel_launch(void* const* d_in, const int* in_sizes, int n_in,
                              void* d_out, int out_size) {
    const float* x   = (const float*)d_in[0];
    const float* w   = (const float*)d_in[1];
    const float* b   = (const float*)d_in[2];
    const void*  hx  = d_in[3];   // int64 or int32, detected on-device
    float*       out = (float*)d_out;

    cudaFuncSetAttribute(lm_mma, cudaFuncAttributeMaxDynamicSharedMemorySize, SMEM_BYTES);

    lm_prep<<<NH, THREADS>>>(hx);
    lm_mma<<<NH * 8, THREADS, SMEM_BYTES>>>(x, w, b, out);
}